// round 6
// baseline (speedup 1.0000x reference)
#include <cuda_runtime.h>

#define B_EX   16384
#define NEG    10
#define E_DIM  128
#define WARPS_PER_BLOCK 8
#define THREADS (WARPS_PER_BLOCK * 32)
#define EX_PER_WARP 2
#define NBLOCKS (B_EX / (WARPS_PER_BLOCK * EX_PER_WARP))   // 1024

// Scratch (allocation-free __device__ globals per harness rules)
__device__ float        g_partials[NBLOCKS];
__device__ unsigned int g_count = 0;

__device__ __forceinline__ float log_sigmoid(float x) {
    return fminf(x, 0.0f) - log1pf(expf(-fabsf(x)));
}

__device__ __forceinline__ float warp_sum(float v) {
#pragma unroll
    for (int off = 16; off > 0; off >>= 1)
        v += __shfl_xor_sync(0xffffffffu, v, off);
    return v;
}

__device__ __forceinline__ float dot4(float4 a, float4 b) {
    return a.x * b.x + a.y * b.y + a.z * b.z + a.w * b.w;
}

__global__ void __launch_bounds__(THREADS)
w2v_fused_kernel(const int*    __restrict__ input_word,
                 const int*    __restrict__ context_word,
                 const int*    __restrict__ noise_words,
                 const float4* __restrict__ W_in,
                 const float4* __restrict__ W_ctx,
                 float*        __restrict__ out)
{
    const int lane    = threadIdx.x & 31;
    const int warp_in = threadIdx.x >> 5;
    const int b0      = (blockIdx.x * WARPS_PER_BLOCK + warp_in) * EX_PER_WARP;
    const int b1      = b0 + 1;

    // --- all index loads up front (independent; one latency exposure) ---
    const int ci0 = input_word[b0];
    const int xi0 = context_word[b0];
    const int ci1 = input_word[b1];
    const int xi1 = context_word[b1];
    int n0[NEG], n1[NEG];
#pragma unroll
    for (int k = 0; k < NEG; k++) n0[k] = noise_words[b0 * NEG + k];
#pragma unroll
    for (int k = 0; k < NEG; k++) n1[k] = noise_words[b1 * NEG + k];

    // --- example 0 gathers (12 rows in flight) ---
    float4 c0 = W_in [(size_t)ci0 * 32 + lane];
    float4 x0 = W_ctx[(size_t)xi0 * 32 + lane];
    float4 nv[NEG];
#pragma unroll
    for (int k = 0; k < NEG; k++)
        nv[k] = W_ctx[(size_t)n0[k] * 32 + lane];

    // --- example 0 per-lane partials (frees nv) ---
    float pos0 = dot4(c0, x0);
    float s0[NEG];
#pragma unroll
    for (int k = 0; k < NEG; k++) s0[k] = dot4(c0, nv[k]);

    // --- example 1 gathers issue here; latency hidden under ex0 reduction ---
    float4 c1 = W_in [(size_t)ci1 * 32 + lane];
    float4 x1 = W_ctx[(size_t)xi1 * 32 + lane];
#pragma unroll
    for (int k = 0; k < NEG; k++)
        nv[k] = W_ctx[(size_t)n1[k] * 32 + lane];

    // --- example 0 warp reduction + loss (overlaps ex1 gather latency) ---
    pos0 = warp_sum(pos0);
#pragma unroll
    for (int k = 0; k < NEG; k++) s0[k] = warp_sum(s0[k]);
    float v0 = 0.0f;
    if (lane == 0) {
        v0 = -log_sigmoid(pos0);
#pragma unroll
        for (int k = 0; k < NEG; k++) v0 -= log_sigmoid(-s0[k]);
    }

    // --- example 1 partials + reduction + loss ---
    float pos1 = dot4(c1, x1);
    float s1[NEG];
#pragma unroll
    for (int k = 0; k < NEG; k++) s1[k] = dot4(c1, nv[k]);

    pos1 = warp_sum(pos1);
#pragma unroll
    for (int k = 0; k < NEG; k++) s1[k] = warp_sum(s1[k]);

    __shared__ float s_warp[WARPS_PER_BLOCK];
    if (lane == 0) {
        float v1 = -log_sigmoid(pos1);
#pragma unroll
        for (int k = 0; k < NEG; k++) v1 -= log_sigmoid(-s1[k]);
        s_warp[warp_in] = v0 + v1;
    }
    __syncthreads();

    // ---- fused finalize: last block reduces all partials ----
    __shared__ bool s_is_last;
    if (threadIdx.x == 0) {
        float t = 0.0f;
#pragma unroll
        for (int i = 0; i < WARPS_PER_BLOCK; i++) t += s_warp[i];
        g_partials[blockIdx.x] = t;
        unsigned int v;
        asm volatile("atom.release.gpu.global.add.u32 %0, [%1], 1;"
                     : "=r"(v) : "l"(&g_count) : "memory");
        s_is_last = (v == (unsigned int)(NBLOCKS - 1));
    }
    __syncthreads();

    if (s_is_last) {
        asm volatile("fence.acquire.gpu;" ::: "memory");
        volatile float* gp = g_partials;
        float t = 0.0f;
#pragma unroll
        for (int j = 0; j < NBLOCKS / THREADS; j++)     // 4 iterations
            t += gp[threadIdx.x + j * THREADS];

        __shared__ float s_red[THREADS];
        s_red[threadIdx.x] = t;
        __syncthreads();
#pragma unroll
        for (int step = THREADS / 2; step > 0; step >>= 1) {
            if (threadIdx.x < step) s_red[threadIdx.x] += s_red[threadIdx.x + step];
            __syncthreads();
        }
        if (threadIdx.x == 0) {
            out[0]  = s_red[0] / (float)B_EX;
            g_count = 0;                   // reset for next graph replay
        }
    }
}

extern "C" void kernel_launch(void* const* d_in, const int* in_sizes, int n_in,
                              void* d_out, int out_size)
{
    const int*    input_word   = (const int*)   d_in[0];
    const int*    context_word = (const int*)   d_in[1];
    const int*    noise_words  = (const int*)   d_in[2];
    const float4* W_in         = (const float4*)d_in[3];
    const float4* W_ctx        = (const float4*)d_in[4];
    float* out = (float*)d_out;

    w2v_fused_kernel<<<NBLOCKS, THREADS>>>(input_word, context_word,
                                           noise_words, W_in, W_ctx, out);
}